// round 6
// baseline (speedup 1.0000x reference)
#include <cuda_runtime.h>
#include <cuda_bf16.h>
#include <math.h>
#include <stdint.h>

#define BB    4
#define SQ    1024
#define NTOK  4096
#define DM    1024
#define DS    128
#define NHEAD 16
#define DH    64
#define MAXK  128
#define KSTR  256          // per-token stride of kept-neuron lists
#define ATPAD 68           // smem row pad (floats) for attention tiles

// ---------------------------------------------------------------------------
// Device-global scratch (no dynamic allocation allowed)
// ---------------------------------------------------------------------------
__device__ float g_emb[16384 * DS];
__device__ float g_ce[3 * 64 * DS];
__device__ float g_h1[NTOK * DM];
__device__ float g_hall[NTOK * 384];
__device__ float g_tau3[NTOK * 3];
__device__ float g_Qm[NTOK * DM];
__device__ float g_Km[NTOK * DM];
__device__ float g_Vm[NTOK * DM];
__device__ float g_attn[NTOK * DM];
__device__ float g_xmid[NTOK * DM];
__device__ float g_h2[NTOK * DM];
__device__ float g_hknow[NTOK * DS];
__device__ float g_tauk[NTOK];
__device__ int   g_ids[4 * NTOK * KSTR];
__device__ float g_vals[4 * NTOK * KSTR];
__device__ int   g_cnt[4 * NTOK];
__device__ float g_cfreq[4 * 64];
__device__ float g_nsum[3 * 4096 + 8192];   // 20480

// ---------------------------------------------------------------------------
__global__ void zero_kernel(float* cfreq, float* nsum)
{
    int i = blockIdx.x * blockDim.x + threadIdx.x;
    if (i < 256)   cfreq[i] = 0.f;
    if (i < 20480) nsum[i]  = 0.f;
}

// normalize 128-wide rows: dst = src / (||src|| + 1e-8)
__global__ void norm_rows(const float* __restrict__ src, float* __restrict__ dst)
{
    const int r = blockIdx.x, tid = threadIdx.x;   // 128 threads
    __shared__ float red[128];
    float v = src[(size_t)r * DS + tid];
    red[tid] = v * v;
    __syncthreads();
    for (int off = 64; off; off >>= 1) {
        if (tid < off) red[tid] += red[tid + off];
        __syncthreads();
    }
    float nrm = sqrtf(red[0]) + 1e-8f;
    dst[(size_t)r * DS + tid] = v / nrm;
}

// LayerNorm over 1024 dims, eps=1e-6
__global__ void ln_kernel(const float* __restrict__ x, const float* __restrict__ sc,
                          const float* __restrict__ bi, float* __restrict__ out)
{
    const int tok = blockIdx.x, tid = threadIdx.x;  // 256 threads
    __shared__ float red[256];
    __shared__ float mean_s, rstd_s;
    float4 v = ((const float4*)(x + (size_t)tok * DM))[tid];
    red[tid] = v.x + v.y + v.z + v.w;
    __syncthreads();
    for (int off = 128; off; off >>= 1) { if (tid < off) red[tid] += red[tid + off]; __syncthreads(); }
    if (tid == 0) mean_s = red[0] * (1.f / DM);
    __syncthreads();
    float mu = mean_s;
    float d0 = v.x - mu, d1 = v.y - mu, d2 = v.z - mu, d3 = v.w - mu;
    red[tid] = d0 * d0 + d1 * d1 + d2 * d2 + d3 * d3;
    __syncthreads();
    for (int off = 128; off; off >>= 1) { if (tid < off) red[tid] += red[tid + off]; __syncthreads(); }
    if (tid == 0) rstd_s = rsqrtf(red[0] * (1.f / DM) + 1e-6f);
    __syncthreads();
    float rs = rstd_s;
    float4 s4 = ((const float4*)sc)[tid];
    float4 b4 = ((const float4*)bi)[tid];
    float4 o;
    o.x = d0 * rs * s4.x + b4.x;
    o.y = d1 * rs * s4.y + b4.y;
    o.z = d2 * rs * s4.z + b4.z;
    o.w = d3 * rs * s4.w + b4.w;
    ((float4*)(out + (size_t)tok * DM))[tid] = o;
}

// tiny projection: out[tok, o] = h[tok] . W[:, o] + b[o]  (one warp per token)
__global__ void tau_kernel(const float* __restrict__ h, const float* __restrict__ W,
                           const float* __restrict__ bvec, float* __restrict__ out, int ntau)
{
    const int tok = blockIdx.x, lane = threadIdx.x;
    const float* hr = h + (size_t)tok * DM;
    for (int o = 0; o < ntau; o++) {
        float p = 0.f;
        for (int d = lane; d < DM; d += 32) p += hr[d] * W[(size_t)d * ntau + o];
        #pragma unroll
        for (int off = 16; off; off >>= 1) p += __shfl_xor_sync(0xffffffffu, p, off);
        if (lane == 0) out[(size_t)tok * ntau + o] = p + bvec[o];
    }
}

// ---------------------------------------------------------------------------
// SGEMM: C = A(MxK)@B(KxN) [+bias(N)] [+res(MxN)]; M%64==0, N%64==0, K%16==0
// ---------------------------------------------------------------------------
__global__ __launch_bounds__(256) void sgemm_kernel(
    const float* __restrict__ A, const float* __restrict__ Bm,
    const float* __restrict__ bias, const float* __restrict__ res,
    float* __restrict__ C, int M, int N, int Kd)
{
    __shared__ float As[16][64];
    __shared__ float Bs[16][64];
    const int bn = blockIdx.x * 64, bm = blockIdx.y * 64;
    const int tid = threadIdx.x;
    const int tx = tid & 15, ty = tid >> 4;
    const int ra = tid >> 2, ca = (tid & 3) * 4;
    const int rb = tid >> 4, cb = (tid & 15) * 4;
    float acc[4][4] = {};
    for (int k0 = 0; k0 < Kd; k0 += 16) {
        float4 a = *(const float4*)(A + (size_t)(bm + ra) * Kd + k0 + ca);
        As[ca + 0][ra] = a.x; As[ca + 1][ra] = a.y; As[ca + 2][ra] = a.z; As[ca + 3][ra] = a.w;
        *(float4*)&Bs[rb][cb] = *(const float4*)(Bm + (size_t)(k0 + rb) * N + bn + cb);
        __syncthreads();
        #pragma unroll
        for (int k = 0; k < 16; k++) {
            float4 av = *(const float4*)&As[k][ty * 4];
            float4 bv = *(const float4*)&Bs[k][tx * 4];
            acc[0][0] += av.x*bv.x; acc[0][1] += av.x*bv.y; acc[0][2] += av.x*bv.z; acc[0][3] += av.x*bv.w;
            acc[1][0] += av.y*bv.x; acc[1][1] += av.y*bv.y; acc[1][2] += av.y*bv.z; acc[1][3] += av.y*bv.w;
            acc[2][0] += av.z*bv.x; acc[2][1] += av.z*bv.y; acc[2][2] += av.z*bv.z; acc[2][3] += av.z*bv.w;
            acc[3][0] += av.w*bv.x; acc[3][1] += av.w*bv.y; acc[3][2] += av.w*bv.z; acc[3][3] += av.w*bv.w;
        }
        __syncthreads();
    }
    #pragma unroll
    for (int i = 0; i < 4; i++) {
        int row = bm + ty * 4 + i;
        #pragma unroll
        for (int j = 0; j < 4; j++) {
            int col = bn + tx * 4 + j;
            float v = acc[i][j];
            if (bias) v += bias[col];
            if (res)  v += res[(size_t)row * N + col];
            C[(size_t)row * N + col] = v;
        }
    }
}

// ---------------------------------------------------------------------------
// Hierarchical gate: one token per block, 256 threads.
// ---------------------------------------------------------------------------
__global__ __launch_bounds__(256) void gate_kernel(
    const float* __restrict__ h, int hstride,
    const float* __restrict__ tau, int taustride,
    const float* __restrict__ emb,
    const float* __restrict__ ce,
    int csh, int n_active,
    float* __restrict__ cfreq, float* __restrict__ nsum,
    int* __restrict__ out_ids, float* __restrict__ out_vals, int* __restrict__ out_cnt)
{
    const int tok = blockIdx.x, tid = threadIdx.x;
    const int w = tid >> 5, lane = tid & 31;
    __shared__ __align__(16) float h_s[DS];
    __shared__ float cscore[64], csel[64];
    __shared__ int   topc[8];
    __shared__ float eg[1024];
    __shared__ float srt[1024];
    __shared__ float red[256];
    __shared__ int   wcnt[8];
    __shared__ int   base_s;
    __shared__ float gsum_s;

    const float tauv = tau[(size_t)tok * taustride];
    if (tid < 32) ((float4*)h_s)[tid] = ((const float4*)(h + (size_t)tok * hstride))[tid];
    __syncthreads();

    // ---- cluster scores: 4-lane groups, one cluster each
    {
        int c = tid >> 2, q = tid & 3;
        const float4* ce4 = (const float4*)(ce + (size_t)c * DS);
        const float4* h4  = (const float4*)h_s;
        float p = 0.f;
        #pragma unroll
        for (int k = 0; k < 8; k++) {
            float4 a = ce4[q + 4 * k], b = h4[q + 4 * k];
            p += a.x*b.x + a.y*b.y + a.z*b.z + a.w*b.w;
        }
        p += __shfl_xor_sync(0xffffffffu, p, 1);
        p += __shfl_xor_sync(0xffffffffu, p, 2);
        if (q == 0) cscore[c] = p;
    }
    __syncthreads();

    // ---- softmax over 64 clusters -> cfreq atomics
    if (tid < 32) {
        float a = cscore[tid], b = cscore[tid + 32];
        float mx = fmaxf(a, b);
        #pragma unroll
        for (int off = 16; off; off >>= 1) mx = fmaxf(mx, __shfl_xor_sync(0xffffffffu, mx, off));
        float ea = expf(a - mx), eb = expf(b - mx);
        float s = ea + eb;
        #pragma unroll
        for (int off = 16; off; off >>= 1) s += __shfl_xor_sync(0xffffffffu, s, off);
        float inv = 1.f / s;
        atomicAdd(&cfreq[tid],      ea * inv);
        atomicAdd(&cfreq[tid + 32], eb * inv);
    }
    if (tid < 64) csel[tid] = cscore[tid];
    __syncthreads();

    // ---- top-8 clusters (warp 0), tie -> lower index
    if (tid < 32) {
        for (int it = 0; it < 8; it++) {
            float a = csel[tid]; int ia = tid;
            float b = csel[tid + 32];
            if (b > a) { a = b; ia = tid + 32; }
            #pragma unroll
            for (int off = 16; off; off >>= 1) {
                float oa = __shfl_xor_sync(0xffffffffu, a, off);
                int   oi = __shfl_xor_sync(0xffffffffu, ia, off);
                if (oa > a || (oa == a && oi < ia)) { a = oa; ia = oi; }
            }
            if (tid == 0) { topc[it] = ia; csel[ia] = -3.4e38f; }
            __syncwarp();
        }
    }
    __syncthreads();

    // ---- active-neuron scores -> eg (8-lane groups, one neuron each)
    {
        int g8 = tid >> 3, r = tid & 7;
        const float4* h4 = (const float4*)h_s;
        const int cmask = (1 << csh) - 1;
        for (int a = g8; a < n_active; a += 32) {
            int cl  = topc[a >> csh];
            int nid = (cl << csh) + (a & cmask);
            const float4* e4 = (const float4*)(emb + (size_t)nid * DS);
            float p = 0.f;
            #pragma unroll
            for (int k = 0; k < 4; k++) {
                float4 va = e4[r + 8 * k], vb = h4[r + 8 * k];
                p += va.x*vb.x + va.y*vb.y + va.z*vb.z + va.w*vb.w;
            }
            p += __shfl_xor_sync(0xffffffffu, p, 1);
            p += __shfl_xor_sync(0xffffffffu, p, 2);
            p += __shfl_xor_sync(0xffffffffu, p, 4);
            if (r == 0) {
                float raw  = p - tauv;
                float gate = raw > 0.f ? raw : 1e-8f * expf(raw);
                eg[a] = expf(gate) - 1.0f;
            }
        }
    }
    __syncthreads();

    // ---- bitonic sort (descending) to find 128th-largest threshold
    for (int i = tid; i < n_active; i += 256) srt[i] = eg[i];
    __syncthreads();
    for (int k = 2; k <= n_active; k <<= 1) {
        for (int j = k >> 1; j; j >>= 1) {
            for (int i = tid; i < n_active; i += 256) {
                int l = i ^ j;
                if (l > i) {
                    float a = srt[i], b = srt[l];
                    bool up = ((i & k) == 0);
                    if (up ? (a < b) : (a > b)) { srt[i] = b; srt[l] = a; }
                }
            }
            __syncthreads();
        }
    }
    const float thr  = srt[MAXK - 1];
    const float gmax = srt[0];

    // ---- gate_sum over kept entries
    {
        float ps = 0.f;
        for (int i = tid; i < n_active; i += 256) { float v = eg[i]; if (v >= thr) ps += v; }
        red[tid] = ps;
        __syncthreads();
        for (int off = 128; off; off >>= 1) { if (tid < off) red[tid] += red[tid + off]; __syncthreads(); }
        if (tid == 0) { gsum_s = red[0]; base_s = 0; }
    }
    __syncthreads();
    const float inv = tanhf(gmax) / (gsum_s + 1e-8f);

    // ---- deterministic index-ordered compaction of kept POSITIVE neurons.
    // v == 0 entries contribute exactly 0 to output/sum/nsum in the reference,
    // so they are skipped; this also bounds the kept count: thr>0 -> ~128,
    // thr==0 -> (#positives) < 128.
    {
        const int cmask = (1 << csh) - 1;
        for (int base = 0; base < n_active; base += 256) {
            int i = base + tid;
            float v = eg[i];
            bool keep = (v >= thr) && (v > 0.f);
            unsigned bal = __ballot_sync(0xffffffffu, keep);
            if (lane == 0) wcnt[w] = __popc(bal);
            __syncthreads();
            int wofs = 0;
            #pragma unroll
            for (int q = 0; q < 8; q++) if (q < w) wofs += wcnt[q];
            int chunk_total = 0;
            #pragma unroll
            for (int q = 0; q < 8; q++) chunk_total += wcnt[q];
            if (keep) {
                int slot = base_s + wofs + __popc(bal & ((1u << lane) - 1u));
                if (slot < KSTR) {
                    int cl  = topc[i >> csh];
                    int nid = (cl << csh) + (i & cmask);
                    float g = v * inv;
                    out_ids [(size_t)tok * KSTR + slot] = nid;
                    out_vals[(size_t)tok * KSTR + slot] = g;
                    atomicAdd(&nsum[nid], g);
                }
            }
            __syncthreads();
            if (tid == 0) base_s += chunk_total;
            __syncthreads();
        }
    }
    if (tid == 0) out_cnt[tok] = min(base_s, KSTR);
}

// ---------------------------------------------------------------------------
// Sparse sense_emit: out[tok] = sum_j (h.n_j) * g_j * n_j  (+ optional res)
// One token per block, 256 threads = 8 warps, warp-per-neuron.
// ---------------------------------------------------------------------------
__global__ __launch_bounds__(256) void emit_kernel(
    const float* __restrict__ h, const float* __restrict__ neurons,
    const int* __restrict__ ids, const float* __restrict__ vals,
    const int* __restrict__ cnt, const float* __restrict__ res,
    float* __restrict__ out)
{
    const int tok = blockIdx.x;
    const int tid = threadIdx.x, w = tid >> 5, lane = tid & 31;
    __shared__ float part[8 * DM];

    const float4* h4 = (const float4*)(h + (size_t)tok * DM);
    float4 hx[8], acc[8];
    #pragma unroll
    for (int k = 0; k < 8; k++) {
        hx[k] = h4[k * 32 + lane];
        acc[k] = make_float4(0.f, 0.f, 0.f, 0.f);
    }
    const int n = cnt[tok];
    const int*   idp = ids  + (size_t)tok * KSTR;
    const float* vp  = vals + (size_t)tok * KSTR;

    for (int j = w; j < n; j += 8) {
        int id = idp[j]; float g = vp[j];
        const float4* r4 = (const float4*)(neurons + (size_t)id * DM);
        float4 v[8]; float p = 0.f;
        #pragma unroll
        for (int k = 0; k < 8; k++) {
            v[k] = r4[k * 32 + lane];
            p += v[k].x*hx[k].x + v[k].y*hx[k].y + v[k].z*hx[k].z + v[k].w*hx[k].w;
        }
        #pragma unroll
        for (int off = 16; off; off >>= 1) p += __shfl_xor_sync(0xffffffffu, p, off);
        float c = p * g;
        #pragma unroll
        for (int k = 0; k < 8; k++) {
            acc[k].x += c * v[k].x; acc[k].y += c * v[k].y;
            acc[k].z += c * v[k].z; acc[k].w += c * v[k].w;
        }
    }
    float4* mp = (float4*)(part + (size_t)w * DM);
    #pragma unroll
    for (int k = 0; k < 8; k++) mp[k * 32 + lane] = acc[k];
    __syncthreads();

    float4 s = make_float4(0.f, 0.f, 0.f, 0.f);
    #pragma unroll
    for (int w2 = 0; w2 < 8; w2++) {
        float4 t = ((const float4*)(part + (size_t)w2 * DM))[tid];
        s.x += t.x; s.y += t.y; s.z += t.z; s.w += t.w;
    }
    if (res) {
        float4 t = ((const float4*)(res + (size_t)tok * DM))[tid];
        s.x += t.x; s.y += t.y; s.z += t.z; s.w += t.w;
    }
    ((float4*)(out + (size_t)tok * DM))[tid] = s;
}

// ---------------------------------------------------------------------------
// Causal flash attention, fp32. Block = (b*h, q_tile of 64), 256 threads.
// ---------------------------------------------------------------------------
__global__ __launch_bounds__(256) void attn_kernel(
    const float* __restrict__ Qm, const float* __restrict__ Km,
    const float* __restrict__ Vm, float* __restrict__ Om)
{
    extern __shared__ float sm[];
    float* QT = sm;                      // [64][ATPAD]  (d-major)
    float* KT = QT + 64 * ATPAD;         // [64][ATPAD]
    float* Ps = KT + 64 * ATPAD;         // [64][ATPAD]  (r-major)
    float* Vs = Ps + 64 * ATPAD;         // [64][64]

    const int bh = blockIdx.x;
    const int b = bh >> 4, hh = bh & 15;
    const int qt = blockIdx.y;
    const int tid = threadIdx.x;
    const int tx = tid & 15, ty = tid >> 4;
    const int q0 = qt * 64;

    // load Q transposed
    #pragma unroll
    for (int p = 0; p < 4; p++) {
        int f = tid + p * 256;
        int r = f >> 4, d4 = (f & 15) * 4;
        float4 v = *(const float4*)(Qm + ((size_t)(b * SQ + q0 + r)) * DM + hh * DH + d4);
        QT[(d4 + 0) * ATPAD + r] = v.x;
        QT[(d4 + 1) * ATPAD + r] = v.y;
        QT[(d4 + 2) * ATPAD + r] = v.z;
        QT[(d4 + 3) * ATPAD + r] = v.w;
    }

    float m[4], l[4], acc[4][4];
    #pragma unroll
    for (int i = 0; i < 4; i++) {
        m[i] = -3.4e38f; l[i] = 0.f;
        #pragma unroll
        for (int j = 0; j < 4; j++) acc[i][j] = 0.f;
    }

    const int ktiles = qt + 1;
    for (int kt = 0; kt < ktiles; kt++) {
        __syncthreads();
        #pragma unroll
        for (int p = 0; p < 4; p++) {
            int f = tid + p * 256;
            int r = f >> 4, d4 = (f & 15) * 4;
            size_t base = ((size_t)(b * SQ + kt * 64 + r)) * DM + hh * DH + d4;
            float4 kv = *(const float4*)(Km + base);
            KT[(d4 + 0) * ATPAD + r] = kv.x;
            KT[(d4 + 1) * ATPAD + r] = kv.y;
            KT[(d4 + 2) * ATPAD + r] = kv.z;
            KT[(d4 + 3) * ATPAD + r] = kv.w;
            float4 vv = *(const float4*)(Vm + base);
            *(float4*)&Vs[r * 64 + d4] = vv;
        }
        __syncthreads();

        // S = Q K^T * 0.125
        float s[4][4] = {};
        #pragma unroll 4
        for (int d = 0; d < 64; d++) {
            float4 av = *(const float4*)&QT[d * ATPAD + ty * 4];
            float4 bv = *(const float4*)&KT[d * ATPAD + tx * 4];
            s[0][0] += av.x*bv.x; s[0][1] += av.x*bv.y; s[0][2] += av.x*bv.z; s[0][3] += av.x*bv.w;
            s[1][0] += av.y*bv.x; s[1][1] += av.y*bv.y; s[1][2] += av.y*bv.z; s[1][3] += av.y*bv.w;
            s[2][0] += av.z*bv.x; s[2][1] += av.z*bv.y; s[2][2] += av.z*bv.z; s[2][3] += av.z*bv.w;
            s[3][0] += av.w*bv.x; s[3][1] += av.w*bv.y; s[3][2] += av.w*bv.z; s[3][3] += av.w*bv.w;
        }
        #pragma unroll
        for (int i = 0; i < 4; i++)
            #pragma unroll
            for (int j = 0; j < 4; j++) s[i][j] *= 0.125f;
        if (kt == qt) {
            #pragma unroll
            for (int i = 0; i < 4; i++)
                #pragma unroll
                for (int j = 0; j < 4; j++)
                    if (kt * 64 + tx * 4 + j > q0 + ty * 4 + i) s[i][j] = -3.0e38f;
        }

        // online softmax update per row
        #pragma unroll
        for (int i = 0; i < 4; i++) {
            float rmax = fmaxf(fmaxf(s[i][0], s[i][1]), fmaxf(s[i][2], s[i][3]));
            #pragma unroll
            for (int off = 1; off < 16; off <<= 1)
                rmax = fmaxf(rmax, __shfl_xor_sync(0xffffffffu, rmax, off));
            float mnew  = fmaxf(m[i], rmax);
            float alpha = expf(m[i] - mnew);
            float rsum = 0.f;
            #pragma unroll
            for (int j = 0; j < 4; j++) {
                float p = expf(s[i][j] - mnew);
                Ps[(ty * 4 + i) * ATPAD + tx * 4 + j] = p;
                rsum += p;
            }
            #pragma unroll
            for (int off = 1; off < 16; off <<= 1)
                rsum += __shfl_xor_sync(0xffffffffu, rsum, off);
            l[i] = l[i] * alpha + rsum;
            m[i] = mnew;
            #pragma unroll
            for (int j = 0; j < 4; j++) acc[i][j] *= alpha;
        }
        __syncthreads();

        // O += P V
        #pragma unroll 4
        for (int k = 0; k < 64; k++) {
            float4 vv = *(const float4*)&Vs[k * 64 + tx * 4];
            float p0 = Ps[(ty * 4 + 0) * ATPAD + k];
            float p1 = Ps[(ty * 4 + 1) * ATPAD + k];
            float p2 = Ps[(ty * 4 + 2) * ATPAD + k];
            float p3 = Ps[(ty * 4 + 3) * ATPAD + k];
            acc[0][0] += p0*vv.x; acc[0][1] += p0*vv.y; acc[0][2] += p0*vv.z; acc[0][3] += p0*vv.w;
            acc[1][0] += p1*vv.x; acc[1][1] += p1*vv.y; acc[1][2] += p1*vv.z; acc[1][3] += p1*vv.w;
            acc[2][0] += p2*vv.x; acc[2][1] += p2*vv.y; acc[2][2] += p2*vv.z; acc[2][3] += p2*vv.w;
            acc[3][0] += p3*vv.x; acc[3][1] += p3*vv.y; acc[3][2] += p3*vv.z; acc[3][3] += p3*vv.w;
        }
    }

    #pragma unroll
    for (int i = 0; i < 4; i++) {
        float invl = 1.f / l[i];
        float4 o;
        o.x = acc[i][0] * invl; o.y = acc[i][1] * invl;
        o.z = acc[i][2] * invl; o.w = acc[i][3] * invl;
        *(float4*)(Om + ((size_t)(b * SQ + q0 + ty * 4 + i)) * DM + hh * DH + tx * 4) = o;
    }
}

// ---------------------------------------------------------------------------
__global__ void aux_kernel(const float* __restrict__ cfreq, const float* __restrict__ nsum,
                           float* __restrict__ out)
{
    const int tid = threadIdx.x;   // 256
    double a = 0.0;
    {
        double f = (double)cfreq[tid] / NTOK;
        double d = f - 1.0 / 64.0;
        a += d * d * 64.0;
    }
    for (int i = tid; i < 20480; i += 256) {
        double n = (i < 12288) ? 4096.0 : 8192.0;
        double f = (double)nsum[i] / NTOK;
        double d = f - 1.0 / n;
        a += d * d * n;
    }
    __shared__ double r[256];
    r[tid] = a;
    __syncthreads();
    for (int off = 128; off; off >>= 1) { if (tid < off) r[tid] += r[tid + off]; __syncthreads(); }
    if (tid == 0) out[0] = (float)r[0];
}

// ---------------------------------------------------------------------------
extern "C" void kernel_launch(void* const* d_in, const int* in_sizes, int n_in,
                              void* d_out, int out_size)
{
    (void)in_sizes; (void)n_in;
    const float* x            = (const float*)d_in[0];
    const float* neuron_emb   = (const float*)d_in[1];
    const float* proj_attn_k  = (const float*)d_in[2];
    const float* proj_attn_b  = (const float*)d_in[3];
    const float* tau_attn_k   = (const float*)d_in[4];
    const float* tau_attn_b   = (const float*)d_in[5];
    const float* proj_know_k  = (const float*)d_in[6];
    const float* proj_know_b  = (const float*)d_in[7];
    const float* tau_know_k   = (const float*)d_in[8];
    const float* tau_know_b   = (const float*)d_in[9];
    const float* ce_qk_in     = (const float*)d_in[10];
    const float* ce_v_in      = (const float*)d_in[11];
    const float* ce_know_in   = (const float*)d_in[12];
    const float* qk_neurons   = (const float*)d_in[13];
    const float* v_neurons    = (const float*)d_in[14];
    const float* know_neurons = (const float*)d_in[15];
    const float* expand_O     = (const float*)d_in[16];
    const float* ln1_scale    = (const float*)d_in[17];
    const float* ln1_bias     = (const float*)d_in[18];
    const float* ln2_scale    = (const float*)d_in[19];
    const float* ln2_bias     = (const float*)d_in[20];
    float* out = (float*)d_out;

    float *p_emb, *p_ce, *p_h1, *p_hall, *p_tau3, *p_Qm, *p_Km, *p_Vm, *p_attn,
          *p_xmid, *p_h2, *p_hknow, *p_tauk, *p_vals, *p_cfreq, *p_nsum;
    int *p_ids, *p_cnt;
    cudaGetSymbolAddress((void**)&p_emb,   g_emb);
    cudaGetSymbolAddress((void**)&p_ce,    g_ce);
    cudaGetSymbolAddress((void**)&p_h1,    g_h1);
    cudaGetSymbolAddress((void**)&p_hall,  g_hall);
    cudaGetSymbolAddress((void**)&p_tau3,  g_tau3);
    cudaGetSymbolAddress((void**)&p_Qm,    g_Qm);
    cudaGetSymbolAddress((void**)&p_Km,    g_Km);
    cudaGetSymbolAddress((void**)&p_Vm,    g_Vm);
    cudaGetSymbolAddress((void**)&p_attn,  g_attn);
    cudaGetSymbolAddress((void**)&p_xmid,  g_xmid);
    cudaGetSymbolAddress((void**)&p_h2,    g_h2);
    cudaGetSymbolAddress((void**)&p_hknow, g_hknow);
    cudaGetSymbolAddress((void**)&p_tauk,  g_tauk);
    cudaGetSymbolAddress((void**)&p_ids,   g_ids);
    cudaGetSymbolAddress((void**)&p_vals,  g_vals);
    cudaGetSymbolAddress((void**)&p_cnt,   g_cnt);
    cudaGetSymbolAddress((void**)&p_cfreq, g_cfreq);
    cudaGetSymbolAddress((void**)&p_nsum,  g_nsum);

    // 0. zero aux accumulators
    zero_kernel<<<80, 256>>>(p_cfreq, p_nsum);

    // 1. normalize embeddings
    norm_rows<<<16384, 128>>>(neuron_emb, p_emb);
    norm_rows<<<64, 128>>>(ce_qk_in,   p_ce);
    norm_rows<<<64, 128>>>(ce_v_in,    p_ce + 64 * DS);
    norm_rows<<<64, 128>>>(ce_know_in, p_ce + 128 * DS);

    // 2. LN1, projections
    ln_kernel<<<NTOK, 256>>>(x, ln1_scale, ln1_bias, p_h1);
    {
        dim3 g(384 / 64, NTOK / 64);
        sgemm_kernel<<<g, 256>>>(p_h1, proj_attn_k, proj_attn_b, nullptr, p_hall, NTOK, 384, DM);
    }
    tau_kernel<<<NTOK, 32>>>(p_h1, tau_attn_k, tau_attn_b, p_tau3, 3);

    // 3. gates Q/K/V
    const float* qk_emb = p_emb;
    const float* v_emb  = p_emb + (size_t)4096 * DS;
    const float* kn_emb = p_emb + (size_t)8192 * DS;
    gate_kernel<<<NTOK, 256>>>(p_hall + 0,   384, p_tau3 + 0, 3, qk_emb, p_ce,            6, 512,
                               p_cfreq + 0,   p_nsum + 0,
                               p_ids + 0 * NTOK * KSTR, p_vals + 0 * NTOK * KSTR, p_cnt + 0 * NTOK);
    gate_kernel<<<NTOK, 256>>>(p_hall + 128, 384, p_tau3 + 1, 3, qk_emb, p_ce,            6, 512,
                               p_cfreq + 64,  p_nsum + 4096,
                               p_ids + 1 * NTOK * KSTR, p_vals + 1 * NTOK * KSTR, p_cnt + 1 * NTOK);
    gate_kernel<<<NTOK, 256>>>(p_hall + 256, 384, p_tau3 + 2, 3, v_emb,  p_ce + 64 * DS,  6, 512,
                               p_cfreq + 128, p_nsum + 8192,
                               p_ids + 2 * NTOK * KSTR, p_vals + 2 * NTOK * KSTR, p_cnt + 2 * NTOK);

    // 4. sparse emits -> Q, K, V
    emit_kernel<<<NTOK, 256>>>(p_h1, qk_neurons, p_ids + 0 * NTOK * KSTR, p_vals + 0 * NTOK * KSTR,
                               p_cnt + 0 * NTOK, nullptr, p_Qm);
    emit_kernel<<<NTOK, 256>>>(p_h1, qk_neurons, p_ids + 1 * NTOK * KSTR, p_vals + 1 * NTOK * KSTR,
                               p_cnt + 1 * NTOK, nullptr, p_Km);
    emit_kernel<<<NTOK, 256>>>(p_h1, v_neurons,  p_ids + 2 * NTOK * KSTR, p_vals + 2 * NTOK * KSTR,
                               p_cnt + 2 * NTOK, nullptr, p_Vm);

    // 5. attention
    {
        const int smem = (3 * 64 * ATPAD + 64 * 64) * (int)sizeof(float);
        cudaFuncSetAttribute(attn_kernel, cudaFuncAttributeMaxDynamicSharedMemorySize, smem);
        dim3 g(BB * NHEAD, SQ / 64);
        attn_kernel<<<g, 256, smem>>>(p_Qm, p_Km, p_Vm, p_attn);
    }

    // 6. O-projection + residual
    {
        dim3 g(DM / 64, NTOK / 64);
        sgemm_kernel<<<g, 256>>>(p_attn, expand_O, nullptr, x, p_xmid, NTOK, DM, DM);
    }

    // 7. LN2, know projection + gate + emit (+ residual) -> d_out
    ln_kernel<<<NTOK, 256>>>(p_xmid, ln2_scale, ln2_bias, p_h2);
    {
        dim3 g(DS / 64, NTOK / 64);
        sgemm_kernel<<<g, 256>>>(p_h2, proj_know_k, proj_know_b, nullptr, p_hknow, NTOK, DS, DM);
    }
    tau_kernel<<<NTOK, 32>>>(p_h2, tau_know_k, tau_know_b, p_tauk, 1);
    gate_kernel<<<NTOK, 256>>>(p_hknow, DS, p_tauk, 1, kn_emb, p_ce + 128 * DS, 7, 1024,
                               p_cfreq + 192, p_nsum + 12288,
                               p_ids + 3 * NTOK * KSTR, p_vals + 3 * NTOK * KSTR, p_cnt + 3 * NTOK);
    emit_kernel<<<NTOK, 256>>>(p_h2, know_neurons, p_ids + 3 * NTOK * KSTR, p_vals + 3 * NTOK * KSTR,
                               p_cnt + 3 * NTOK, p_xmid, out);

    // 8. aux scalar
    if (out_size > NTOK * DM)
        aux_kernel<<<1, 256>>>(p_cfreq, p_nsum, out + (size_t)NTOK * DM);
}

// round 12
// speedup vs baseline: 1.0482x; 1.0482x over previous
#include <cuda_runtime.h>
#include <cuda_bf16.h>
#include <cuda_fp16.h>
#include <math.h>
#include <stdint.h>

#define BB    4
#define SQ    1024
#define NTOK  4096
#define DM    1024
#define DS    128
#define NHEAD 16
#define DH    64
#define MAXK  128
#define KSTR  256          // per-token stride of kept-neuron lists
#define ATPAD 68           // smem row pad (floats) for attention tiles

// ---------------------------------------------------------------------------
// Device-global scratch (no dynamic allocation allowed)
// ---------------------------------------------------------------------------
__device__ float g_emb[16384 * DS];
__device__ float g_ce[3 * 64 * DS];
__device__ float g_h1[NTOK * DM];
__device__ float g_hall[NTOK * 384];
__device__ float g_tau3[NTOK * 3];
__device__ float g_Qm[NTOK * DM];
__device__ float g_Km[NTOK * DM];
__device__ float g_Vm[NTOK * DM];
__device__ float g_attn[NTOK * DM];
__device__ float g_xmid[NTOK * DM];
__device__ float g_h2[NTOK * DM];
__device__ float g_hknow[NTOK * DS];
__device__ float g_tauk[NTOK];
__device__ int   g_ids[4 * NTOK * KSTR];
__device__ float g_vals[4 * NTOK * KSTR];
__device__ int   g_cnt[4 * NTOK];
__device__ float g_cfreq[4 * 64];
__device__ float g_nsum[3 * 4096 + 8192];   // 20480
__device__ __half g_qkn_h[4096 * DM];
__device__ __half g_vn_h[4096 * DM];
__device__ __half g_kn_h[8192 * DM];

// ---------------------------------------------------------------------------
__global__ void zero_kernel(float* cfreq, float* nsum)
{
    int i = blockIdx.x * blockDim.x + threadIdx.x;
    if (i < 256)   cfreq[i] = 0.f;
    if (i < 20480) nsum[i]  = 0.f;
}

// fp32 -> fp16 matrix conversion (element order preserved); n4 = n/4
__global__ void f2h_kernel(const float* __restrict__ src, __half* __restrict__ dst, int n4)
{
    int i = blockIdx.x * blockDim.x + threadIdx.x;
    if (i < n4) {
        float4 v = ((const float4*)src)[i];
        __half2* d2 = (__half2*)dst;
        d2[2 * i]     = __floats2half2_rn(v.x, v.y);
        d2[2 * i + 1] = __floats2half2_rn(v.z, v.w);
    }
}

// normalize 128-wide rows: dst = src / (||src|| + 1e-8)
__global__ void norm_rows(const float* __restrict__ src, float* __restrict__ dst)
{
    const int r = blockIdx.x, tid = threadIdx.x;   // 128 threads
    __shared__ float red[128];
    float v = src[(size_t)r * DS + tid];
    red[tid] = v * v;
    __syncthreads();
    for (int off = 64; off; off >>= 1) {
        if (tid < off) red[tid] += red[tid + off];
        __syncthreads();
    }
    float nrm = sqrtf(red[0]) + 1e-8f;
    dst[(size_t)r * DS + tid] = v / nrm;
}

// LayerNorm over 1024 dims, eps=1e-6
__global__ void ln_kernel(const float* __restrict__ x, const float* __restrict__ sc,
                          const float* __restrict__ bi, float* __restrict__ out)
{
    const int tok = blockIdx.x, tid = threadIdx.x;  // 256 threads
    __shared__ float red[256];
    __shared__ float mean_s, rstd_s;
    float4 v = ((const float4*)(x + (size_t)tok * DM))[tid];
    red[tid] = v.x + v.y + v.z + v.w;
    __syncthreads();
    for (int off = 128; off; off >>= 1) { if (tid < off) red[tid] += red[tid + off]; __syncthreads(); }
    if (tid == 0) mean_s = red[0] * (1.f / DM);
    __syncthreads();
    float mu = mean_s;
    float d0 = v.x - mu, d1 = v.y - mu, d2 = v.z - mu, d3 = v.w - mu;
    red[tid] = d0 * d0 + d1 * d1 + d2 * d2 + d3 * d3;
    __syncthreads();
    for (int off = 128; off; off >>= 1) { if (tid < off) red[tid] += red[tid + off]; __syncthreads(); }
    if (tid == 0) rstd_s = rsqrtf(red[0] * (1.f / DM) + 1e-6f);
    __syncthreads();
    float rs = rstd_s;
    float4 s4 = ((const float4*)sc)[tid];
    float4 b4 = ((const float4*)bi)[tid];
    float4 o;
    o.x = d0 * rs * s4.x + b4.x;
    o.y = d1 * rs * s4.y + b4.y;
    o.z = d2 * rs * s4.z + b4.z;
    o.w = d3 * rs * s4.w + b4.w;
    ((float4*)(out + (size_t)tok * DM))[tid] = o;
}

// tiny projection: out[tok, o] = h[tok] . W[:, o] + b[o]  (one warp per token)
__global__ void tau_kernel(const float* __restrict__ h, const float* __restrict__ W,
                           const float* __restrict__ bvec, float* __restrict__ out, int ntau)
{
    const int tok = blockIdx.x, lane = threadIdx.x;
    const float* hr = h + (size_t)tok * DM;
    for (int o = 0; o < ntau; o++) {
        float p = 0.f;
        for (int d = lane; d < DM; d += 32) p += hr[d] * W[(size_t)d * ntau + o];
        #pragma unroll
        for (int off = 16; off; off >>= 1) p += __shfl_xor_sync(0xffffffffu, p, off);
        if (lane == 0) out[(size_t)tok * ntau + o] = p + bvec[o];
    }
}

// ---------------------------------------------------------------------------
// SGEMM: C = A(MxK)@B(KxN) [+bias(N)] [+res(MxN)]; M%64==0, N%64==0, K%16==0
// ---------------------------------------------------------------------------
__global__ __launch_bounds__(256) void sgemm_kernel(
    const float* __restrict__ A, const float* __restrict__ Bm,
    const float* __restrict__ bias, const float* __restrict__ res,
    float* __restrict__ C, int M, int N, int Kd)
{
    __shared__ float As[16][64];
    __shared__ float Bs[16][64];
    const int bn = blockIdx.x * 64, bm = blockIdx.y * 64;
    const int tid = threadIdx.x;
    const int tx = tid & 15, ty = tid >> 4;
    const int ra = tid >> 2, ca = (tid & 3) * 4;
    const int rb = tid >> 4, cb = (tid & 15) * 4;
    float acc[4][4] = {};
    for (int k0 = 0; k0 < Kd; k0 += 16) {
        float4 a = *(const float4*)(A + (size_t)(bm + ra) * Kd + k0 + ca);
        As[ca + 0][ra] = a.x; As[ca + 1][ra] = a.y; As[ca + 2][ra] = a.z; As[ca + 3][ra] = a.w;
        *(float4*)&Bs[rb][cb] = *(const float4*)(Bm + (size_t)(k0 + rb) * N + bn + cb);
        __syncthreads();
        #pragma unroll
        for (int k = 0; k < 16; k++) {
            float4 av = *(const float4*)&As[k][ty * 4];
            float4 bv = *(const float4*)&Bs[k][tx * 4];
            acc[0][0] += av.x*bv.x; acc[0][1] += av.x*bv.y; acc[0][2] += av.x*bv.z; acc[0][3] += av.x*bv.w;
            acc[1][0] += av.y*bv.x; acc[1][1] += av.y*bv.y; acc[1][2] += av.y*bv.z; acc[1][3] += av.y*bv.w;
            acc[2][0] += av.z*bv.x; acc[2][1] += av.z*bv.y; acc[2][2] += av.z*bv.z; acc[2][3] += av.z*bv.w;
            acc[3][0] += av.w*bv.x; acc[3][1] += av.w*bv.y; acc[3][2] += av.w*bv.z; acc[3][3] += av.w*bv.w;
        }
        __syncthreads();
    }
    #pragma unroll
    for (int i = 0; i < 4; i++) {
        int row = bm + ty * 4 + i;
        #pragma unroll
        for (int j = 0; j < 4; j++) {
            int col = bn + tx * 4 + j;
            float v = acc[i][j];
            if (bias) v += bias[col];
            if (res)  v += res[(size_t)row * N + col];
            C[(size_t)row * N + col] = v;
        }
    }
}

// ---------------------------------------------------------------------------
// Hierarchical gate: one token per block, 256 threads.
// ---------------------------------------------------------------------------
__global__ __launch_bounds__(256) void gate_kernel(
    const float* __restrict__ h, int hstride,
    const float* __restrict__ tau, int taustride,
    const float* __restrict__ emb,
    const float* __restrict__ ce,
    int csh, int n_active,
    float* __restrict__ cfreq, float* __restrict__ nsum,
    int* __restrict__ out_ids, float* __restrict__ out_vals, int* __restrict__ out_cnt)
{
    const int tok = blockIdx.x, tid = threadIdx.x;
    const int w = tid >> 5, lane = tid & 31;
    __shared__ __align__(16) float h_s[DS];
    __shared__ float cscore[64], csel[64];
    __shared__ int   topc[8];
    __shared__ float eg[1024];
    __shared__ float red[256];
    __shared__ int   wcnt[8];
    __shared__ int   base_s;
    __shared__ float gsum_s;

    const float tauv = tau[(size_t)tok * taustride];
    if (tid < 32) ((float4*)h_s)[tid] = ((const float4*)(h + (size_t)tok * hstride))[tid];
    __syncthreads();

    // ---- cluster scores: 4-lane groups, one cluster each
    {
        int c = tid >> 2, q = tid & 3;
        const float4* ce4 = (const float4*)(ce + (size_t)c * DS);
        const float4* h4  = (const float4*)h_s;
        float p = 0.f;
        #pragma unroll
        for (int k = 0; k < 8; k++) {
            float4 a = ce4[q + 4 * k], b = h4[q + 4 * k];
            p += a.x*b.x + a.y*b.y + a.z*b.z + a.w*b.w;
        }
        p += __shfl_xor_sync(0xffffffffu, p, 1);
        p += __shfl_xor_sync(0xffffffffu, p, 2);
        if (q == 0) cscore[c] = p;
    }
    __syncthreads();

    // ---- softmax over 64 clusters -> cfreq atomics
    if (tid < 32) {
        float a = cscore[tid], b = cscore[tid + 32];
        float mx = fmaxf(a, b);
        #pragma unroll
        for (int off = 16; off; off >>= 1) mx = fmaxf(mx, __shfl_xor_sync(0xffffffffu, mx, off));
        float ea = expf(a - mx), eb = expf(b - mx);
        float s = ea + eb;
        #pragma unroll
        for (int off = 16; off; off >>= 1) s += __shfl_xor_sync(0xffffffffu, s, off);
        float inv = 1.f / s;
        atomicAdd(&cfreq[tid],      ea * inv);
        atomicAdd(&cfreq[tid + 32], eb * inv);
    }
    if (tid < 64) csel[tid] = cscore[tid];
    __syncthreads();

    // ---- top-8 clusters (warp 0), tie -> lower index
    if (tid < 32) {
        for (int it = 0; it < 8; it++) {
            float a = csel[tid]; int ia = tid;
            float b = csel[tid + 32];
            if (b > a) { a = b; ia = tid + 32; }
            #pragma unroll
            for (int off = 16; off; off >>= 1) {
                float oa = __shfl_xor_sync(0xffffffffu, a, off);
                int   oi = __shfl_xor_sync(0xffffffffu, ia, off);
                if (oa > a || (oa == a && oi < ia)) { a = oa; ia = oi; }
            }
            if (tid == 0) { topc[it] = ia; csel[ia] = -3.4e38f; }
            __syncwarp();
        }
    }
    __syncthreads();

    // ---- active-neuron scores -> eg (8-lane groups, one neuron each)
    {
        int g8 = tid >> 3, r = tid & 7;
        const float4* h4 = (const float4*)h_s;
        const int cmask = (1 << csh) - 1;
        for (int a = g8; a < n_active; a += 32) {
            int cl  = topc[a >> csh];
            int nid = (cl << csh) + (a & cmask);
            const float4* e4 = (const float4*)(emb + (size_t)nid * DS);
            float p = 0.f;
            #pragma unroll
            for (int k = 0; k < 4; k++) {
                float4 va = e4[r + 8 * k], vb = h4[r + 8 * k];
                p += va.x*vb.x + va.y*vb.y + va.z*vb.z + va.w*vb.w;
            }
            p += __shfl_xor_sync(0xffffffffu, p, 1);
            p += __shfl_xor_sync(0xffffffffu, p, 2);
            p += __shfl_xor_sync(0xffffffffu, p, 4);
            if (r == 0) {
                float raw  = p - tauv;
                float gate = raw > 0.f ? raw : 1e-8f * expf(raw);
                eg[a] = expf(gate) - 1.0f;
            }
        }
    }
    __syncthreads();

    // ---- max + EXACT 128th-largest via MSB-first binary search on bit
    // patterns (all eg >= 0, so uint compare is order-isomorphic to float).
    const int nv = n_active >> 8;        // 2 or 4 values per thread
    uint32_t vb[4];
    float lmax = 0.f;
    for (int q = 0; q < nv; q++) {
        float v = eg[q * 256 + tid];
        vb[q] = __float_as_uint(v);
        lmax = fmaxf(lmax, v);
    }
    red[tid] = lmax;
    __syncthreads();
    for (int off = 128; off; off >>= 1) {
        if (tid < off) red[tid] = fmaxf(red[tid], red[tid + off]);
        __syncthreads();
    }
    const float gmax = red[0];
    __syncthreads();

    uint32_t ans = 0u;
    for (int bit = 31; bit >= 0; bit--) {
        uint32_t cand = ans | (1u << bit);
        int c = 0;
        for (int q = 0; q < nv; q++) c += (vb[q] >= cand) ? 1 : 0;
        #pragma unroll
        for (int off = 16; off; off >>= 1) c += __shfl_xor_sync(0xffffffffu, c, off);
        if (lane == 0) wcnt[w] = c;
        __syncthreads();
        int tot = 0;
        #pragma unroll
        for (int q = 0; q < 8; q++) tot += wcnt[q];
        if (tot >= MAXK) ans = cand;
        __syncthreads();
    }
    const float thr = __uint_as_float(ans);

    // ---- gate_sum over kept entries
    {
        float ps = 0.f;
        for (int q = 0; q < nv; q++) { float v = eg[q * 256 + tid]; if (v >= thr) ps += v; }
        red[tid] = ps;
        __syncthreads();
        for (int off = 128; off; off >>= 1) { if (tid < off) red[tid] += red[tid + off]; __syncthreads(); }
        if (tid == 0) { gsum_s = red[0]; base_s = 0; }
    }
    __syncthreads();
    const float inv = tanhf(gmax) / (gsum_s + 1e-8f);

    // ---- deterministic index-ordered compaction of kept POSITIVE neurons.
    {
        const int cmask = (1 << csh) - 1;
        for (int base = 0; base < n_active; base += 256) {
            int i = base + tid;
            float v = eg[i];
            bool keep = (v >= thr) && (v > 0.f);
            unsigned bal = __ballot_sync(0xffffffffu, keep);
            if (lane == 0) wcnt[w] = __popc(bal);
            __syncthreads();
            int wofs = 0;
            #pragma unroll
            for (int q = 0; q < 8; q++) if (q < w) wofs += wcnt[q];
            int chunk_total = 0;
            #pragma unroll
            for (int q = 0; q < 8; q++) chunk_total += wcnt[q];
            if (keep) {
                int slot = base_s + wofs + __popc(bal & ((1u << lane) - 1u));
                if (slot < KSTR) {
                    int cl  = topc[i >> csh];
                    int nid = (cl << csh) + (i & cmask);
                    float g = v * inv;
                    out_ids [(size_t)tok * KSTR + slot] = nid;
                    out_vals[(size_t)tok * KSTR + slot] = g;
                    atomicAdd(&nsum[nid], g);
                }
            }
            __syncthreads();
            if (tid == 0) base_s += chunk_total;
            __syncthreads();
        }
    }
    if (tid == 0) out_cnt[tok] = min(base_s, KSTR);
}

// ---------------------------------------------------------------------------
// Sparse sense_emit with fp16 neuron rows:
//   out[tok] = sum_j (h.n_j) * g_j * n_j  (+ optional res)
// One token per block, 256 threads = 8 warps, warp-per-neuron.
// ---------------------------------------------------------------------------
__global__ __launch_bounds__(256) void emit_kernel(
    const float* __restrict__ h, const __half* __restrict__ neurons,
    const int* __restrict__ ids, const float* __restrict__ vals,
    const int* __restrict__ cnt, const float* __restrict__ res,
    float* __restrict__ out)
{
    const int tok = blockIdx.x;
    const int tid = threadIdx.x, w = tid >> 5, lane = tid & 31;
    __shared__ float part[8 * DM];

    const float4* h4 = (const float4*)(h + (size_t)tok * DM);
    float4 hx[8], acc[8];
    #pragma unroll
    for (int q = 0; q < 4; q++) {
        int fi = (q * 32 + lane) * 2;
        hx[2 * q]     = h4[fi];
        hx[2 * q + 1] = h4[fi + 1];
        acc[2 * q]     = make_float4(0.f, 0.f, 0.f, 0.f);
        acc[2 * q + 1] = make_float4(0.f, 0.f, 0.f, 0.f);
    }
    const int n = cnt[tok];
    const int*   idp = ids  + (size_t)tok * KSTR;
    const float* vp  = vals + (size_t)tok * KSTR;

    for (int j = w; j < n; j += 8) {
        int id = idp[j]; float g = vp[j];
        const uint4* r4 = (const uint4*)(neurons + (size_t)id * DM);  // 128 uint4/row
        float4 nvv[8]; float p = 0.f;
        #pragma unroll
        for (int q = 0; q < 4; q++) {
            uint4 u = r4[q * 32 + lane];                // 8 halves
            float2 f0 = __half22float2(*(const __half2*)&u.x);
            float2 f1 = __half22float2(*(const __half2*)&u.y);
            float2 f2 = __half22float2(*(const __half2*)&u.z);
            float2 f3 = __half22float2(*(const __half2*)&u.w);
            nvv[2 * q]     = make_float4(f0.x, f0.y, f1.x, f1.y);
            nvv[2 * q + 1] = make_float4(f2.x, f2.y, f3.x, f3.y);
            p += nvv[2*q].x*hx[2*q].x + nvv[2*q].y*hx[2*q].y
               + nvv[2*q].z*hx[2*q].z + nvv[2*q].w*hx[2*q].w;
            p += nvv[2*q+1].x*hx[2*q+1].x + nvv[2*q+1].y*hx[2*q+1].y
               + nvv[2*q+1].z*hx[2*q+1].z + nvv[2*q+1].w*hx[2*q+1].w;
        }
        #pragma unroll
        for (int off = 16; off; off >>= 1) p += __shfl_xor_sync(0xffffffffu, p, off);
        float c = p * g;
        #pragma unroll
        for (int k = 0; k < 8; k++) {
            acc[k].x += c * nvv[k].x; acc[k].y += c * nvv[k].y;
            acc[k].z += c * nvv[k].z; acc[k].w += c * nvv[k].w;
        }
    }
    float4* mp = (float4*)(part + (size_t)w * DM);
    #pragma unroll
    for (int q = 0; q < 4; q++) {
        int fi = (q * 32 + lane) * 2;
        mp[fi]     = acc[2 * q];
        mp[fi + 1] = acc[2 * q + 1];
    }
    __syncthreads();

    float4 s = make_float4(0.f, 0.f, 0.f, 0.f);
    #pragma unroll
    for (int w2 = 0; w2 < 8; w2++) {
        float4 t = ((const float4*)(part + (size_t)w2 * DM))[tid];
        s.x += t.x; s.y += t.y; s.z += t.z; s.w += t.w;
    }
    if (res) {
        float4 t = ((const float4*)(res + (size_t)tok * DM))[tid];
        s.x += t.x; s.y += t.y; s.z += t.z; s.w += t.w;
    }
    ((float4*)(out + (size_t)tok * DM))[tid] = s;
}

// ---------------------------------------------------------------------------
// Causal flash attention, fp32. Block = (b*h, q_tile of 64), 256 threads.
// ---------------------------------------------------------------------------
__global__ __launch_bounds__(256) void attn_kernel(
    const float* __restrict__ Qm, const float* __restrict__ Km,
    const float* __restrict__ Vm, float* __restrict__ Om)
{
    extern __shared__ float sm[];
    float* QT = sm;                      // [64][ATPAD]  (d-major)
    float* KT = QT + 64 * ATPAD;         // [64][ATPAD]
    float* Ps = KT + 64 * ATPAD;         // [64][ATPAD]  (r-major)
    float* Vs = Ps + 64 * ATPAD;         // [64][64]

    const int bh = blockIdx.x;
    const int b = bh >> 4, hh = bh & 15;
    const int qt = blockIdx.y;
    const int tid = threadIdx.x;
    const int tx = tid & 15, ty = tid >> 4;
    const int q0 = qt * 64;

    // load Q transposed
    #pragma unroll
    for (int p = 0; p < 4; p++) {
        int f = tid + p * 256;
        int r = f >> 4, d4 = (f & 15) * 4;
        float4 v = *(const float4*)(Qm + ((size_t)(b * SQ + q0 + r)) * DM + hh * DH + d4);
        QT[(d4 + 0) * ATPAD + r] = v.x;
        QT[(d4 + 1) * ATPAD + r] = v.y;
        QT[(d4 + 2) * ATPAD + r] = v.z;
        QT[(d4 + 3) * ATPAD + r] = v.w;
    }

    float m[4], l[4], acc[4][4];
    #pragma unroll
    for (int i = 0; i < 4; i++) {
        m[i] = -3.4e38f; l[i] = 0.f;
        #pragma unroll
        for (int j = 0; j < 4; j++) acc[i][j] = 0.f;
    }

    const int ktiles = qt + 1;
    for (int kt = 0; kt < ktiles; kt++) {
        __syncthreads();
        #pragma unroll
        for (int p = 0; p < 4; p++) {
            int f = tid + p * 256;
            int r = f >> 4, d4 = (f & 15) * 4;
            size_t base = ((size_t)(b * SQ + kt * 64 + r)) * DM + hh * DH + d4;
            float4 kv = *(const float4*)(Km + base);
            KT[(d4 + 0) * ATPAD + r] = kv.x;
            KT[(d4 + 1) * ATPAD + r] = kv.y;
            KT[(d4 + 2) * ATPAD + r] = kv.z;
            KT[(d4 + 3) * ATPAD + r] = kv.w;
            float4 vv = *(const float4*)(Vm + base);
            *(float4*)&Vs[r * 64 + d4] = vv;
        }
        __syncthreads();

        // S = Q K^T * 0.125
        float s[4][4] = {};
        #pragma unroll 4
        for (int d = 0; d < 64; d++) {
            float4 av = *(const float4*)&QT[d * ATPAD + ty * 4];
            float4 bv = *(const float4*)&KT[d * ATPAD + tx * 4];
            s[0][0] += av.x*bv.x; s[0][1] += av.x*bv.y; s[0][2] += av.x*bv.z; s[0][3] += av.x*bv.w;
            s[1][0] += av.y*bv.x; s[1][1] += av.y*bv.y; s[1][2] += av.y*bv.z; s[1][3] += av.y*bv.w;
            s[2][0] += av.z*bv.x; s[2][1] += av.z*bv.y; s[2][2] += av.z*bv.z; s[2][3] += av.z*bv.w;
            s[3][0] += av.w*bv.x; s[3][1] += av.w*bv.y; s[3][2] += av.w*bv.z; s[3][3] += av.w*bv.w;
        }
        #pragma unroll
        for (int i = 0; i < 4; i++)
            #pragma unroll
            for (int j = 0; j < 4; j++) s[i][j] *= 0.125f;
        if (kt == qt) {
            #pragma unroll
            for (int i = 0; i < 4; i++)
                #pragma unroll
                for (int j = 0; j < 4; j++)
                    if (kt * 64 + tx * 4 + j > q0 + ty * 4 + i) s[i][j] = -3.0e38f;
        }

        // online softmax update per row
        #pragma unroll
        for (int i = 0; i < 4; i++) {
            float rmax = fmaxf(fmaxf(s[i][0], s[i][1]), fmaxf(s[i][2], s[i][3]));
            #pragma unroll
            for (int off = 1; off < 16; off <<= 1)
                rmax = fmaxf(rmax, __shfl_xor_sync(0xffffffffu, rmax, off));
            float mnew  = fmaxf(m[i], rmax);
            float alpha = expf(m[i] - mnew);
            float rsum = 0.f;
            #pragma unroll
            for (int j = 0; j < 4; j++) {
                float p = expf(s[i][j] - mnew);
                Ps[(ty * 4 + i) * ATPAD + tx * 4 + j] = p;
                rsum += p;
            }
            #pragma unroll
            for (int off = 1; off < 16; off <<= 1)
                rsum += __shfl_xor_sync(0xffffffffu, rsum, off);
            l[i] = l[i] * alpha + rsum;
            m[i] = mnew;
            #pragma unroll
            for (int j = 0; j < 4; j++) acc[i][j] *= alpha;
        }
        __syncthreads();

        // O += P V
        #pragma unroll 4
        for (int k = 0; k < 64; k++) {
            float4 vv = *(const float4*)&Vs[k * 64 + tx * 4];
            float p0 = Ps[(ty * 4 + 0) * ATPAD + k];
            float p1 = Ps[(ty * 4 + 1) * ATPAD + k];
            float p2 = Ps[(ty * 4 + 2) * ATPAD + k];
            float p3 = Ps[(ty * 4 + 3) * ATPAD + k];
            acc[0][0] += p0*vv.x; acc[0][1] += p0*vv.y; acc[0][2] += p0*vv.z; acc[0][3] += p0*vv.w;
            acc[1][0] += p1*vv.x; acc[1][1] += p1*vv.y; acc[1][2] += p1*vv.z; acc[1][3] += p1*vv.w;
            acc[2][0] += p2*vv.x; acc[2][1] += p2*vv.y; acc[2][2] += p2*vv.z; acc[2][3] += p2*vv.w;
            acc[3][0] += p3*vv.x; acc[3][1] += p3*vv.y; acc[3][2] += p3*vv.z; acc[3][3] += p3*vv.w;
        }
    }

    #pragma unroll
    for (int i = 0; i < 4; i++) {
        float invl = 1.f / l[i];
        float4 o;
        o.x = acc[i][0] * invl; o.y = acc[i][1] * invl;
        o.z = acc[i][2] * invl; o.w = acc[i][3] * invl;
        *(float4*)(Om + ((size_t)(b * SQ + q0 + ty * 4 + i)) * DM + hh * DH + tx * 4) = o;
    }
}

// ---------------------------------------------------------------------------
__global__ void aux_kernel(const float* __restrict__ cfreq, const float* __restrict__ nsum,
                           float* __restrict__ out)
{
    const int tid = threadIdx.x;   // 256
    double a = 0.0;
    {
        double f = (double)cfreq[tid] / NTOK;
        double d = f - 1.0 / 64.0;
        a += d * d * 64.0;
    }
    for (int i = tid; i < 20480; i += 256) {
        double n = (i < 12288) ? 4096.0 : 8192.0;
        double f = (double)nsum[i] / NTOK;
        double d = f - 1.0 / n;
        a += d * d * n;
    }
    __shared__ double r[256];
    r[tid] = a;
    __syncthreads();
    for (int off = 128; off; off >>= 1) { if (tid < off) r[tid] += r[tid + off]; __syncthreads(); }
    if (tid == 0) out[0] = (float)r[0];
}

// ---------------------------------------------------------------------------
extern "C" void kernel_launch(void* const* d_in, const int* in_sizes, int n_in,
                              void* d_out, int out_size)
{
    (void)in_sizes; (void)n_in;
    const float* x            = (const float*)d_in[0];
    const float* neuron_emb   = (const float*)d_in[1];
    const float* proj_attn_k  = (const float*)d_in[2];
    const float* proj_attn_b  = (const float*)d_in[3];
    const float* tau_attn_k   = (const float*)d_in[4];
    const float* tau_attn_b   = (const float*)d_in[5];
    const float* proj_know_k  = (const float*)d_in[6];
    const float* proj_know_b  = (const float*)d_in[7];
    const float* tau_know_k   = (const float*)d_in[8];
    const float* tau_know_b   = (const float*)d_in[9];
    const float* ce_qk_in     = (const float*)d_in[10];
    const float* ce_v_in      = (const float*)d_in[11];
    const float* ce_know_in   = (const float*)d_in[12];
    const float* qk_neurons   = (const float*)d_in[13];
    const float* v_neurons    = (const float*)d_in[14];
    const float* know_neurons = (const float*)d_in[15];
    const float* expand_O     = (const float*)d_in[16];
    const float* ln1_scale    = (const float*)d_in[17];
    const float* ln1_bias     = (const float*)d_in[18];
    const float* ln2_scale    = (const float*)d_in[19];
    const float* ln2_bias     = (const float*)d_in[20];
    float* out = (float*)d_out;

    float *p_emb, *p_ce, *p_h1, *p_hall, *p_tau3, *p_Qm, *p_Km, *p_Vm, *p_attn,
          *p_xmid, *p_h2, *p_hknow, *p_tauk, *p_vals, *p_cfreq, *p_nsum;
    int *p_ids, *p_cnt;
    __half *p_qkn, *p_vn, *p_kn;
    cudaGetSymbolAddress((void**)&p_emb,   g_emb);
    cudaGetSymbolAddress((void**)&p_ce,    g_ce);
    cudaGetSymbolAddress((void**)&p_h1,    g_h1);
    cudaGetSymbolAddress((void**)&p_hall,  g_hall);
    cudaGetSymbolAddress((void**)&p_tau3,  g_tau3);
    cudaGetSymbolAddress((void**)&p_Qm,    g_Qm);
    cudaGetSymbolAddress((void**)&p_Km,    g_Km);
    cudaGetSymbolAddress((void**)&p_Vm,    g_Vm);
    cudaGetSymbolAddress((void**)&p_attn,  g_attn);
    cudaGetSymbolAddress((void**)&p_xmid,  g_xmid);
    cudaGetSymbolAddress((void**)&p_h2,    g_h2);
    cudaGetSymbolAddress((void**)&p_hknow, g_hknow);
    cudaGetSymbolAddress((void**)&p_tauk,  g_tauk);
    cudaGetSymbolAddress((void**)&p_ids,   g_ids);
    cudaGetSymbolAddress((void**)&p_vals,  g_vals);
    cudaGetSymbolAddress((void**)&p_cnt,   g_cnt);
    cudaGetSymbolAddress((void**)&p_cfreq, g_cfreq);
    cudaGetSymbolAddress((void**)&p_nsum,  g_nsum);
    cudaGetSymbolAddress((void**)&p_qkn,   g_qkn_h);
    cudaGetSymbolAddress((void**)&p_vn,    g_vn_h);
    cudaGetSymbolAddress((void**)&p_kn,    g_kn_h);

    // 0. zero aux accumulators; convert neuron matrices to fp16
    zero_kernel<<<80, 256>>>(p_cfreq, p_nsum);
    f2h_kernel<<<(4096 * DM / 4 + 255) / 256, 256>>>(qk_neurons,   p_qkn, 4096 * DM / 4);
    f2h_kernel<<<(4096 * DM / 4 + 255) / 256, 256>>>(v_neurons,    p_vn,  4096 * DM / 4);
    f2h_kernel<<<(8192 * DM / 4 + 255) / 256, 256>>>(know_neurons, p_kn,  8192 * DM / 4);

    // 1. normalize embeddings
    norm_rows<<<16384, 128>>>(neuron_emb, p_emb);
    norm_rows<<<64, 128>>>(ce_qk_in,   p_ce);
    norm_rows<<<64, 128>>>(ce_v_in,    p_ce + 64 * DS);
    norm_rows<<<64, 128>>>(ce_know_in, p_ce + 128 * DS);

    // 2. LN1, projections
    ln_kernel<<<NTOK, 256>>>(x, ln1_scale, ln1_bias, p_h1);
    {
        dim3 g(384 / 64, NTOK / 64);
        sgemm_kernel<<<g, 256>>>(p_h1, proj_attn_k, proj_attn_b, nullptr, p_hall, NTOK, 384, DM);
    }
    tau_kernel<<<NTOK, 32>>>(p_h1, tau_attn_k, tau_attn_b, p_tau3, 3);

    // 3. gates Q/K/V
    const float* qk_emb = p_emb;
    const float* v_emb  = p_emb + (size_t)4096 * DS;
    const float* kn_emb = p_emb + (size_t)8192 * DS;
    gate_kernel<<<NTOK, 256>>>(p_hall + 0,   384, p_tau3 + 0, 3, qk_emb, p_ce,            6, 512,
                               p_cfreq + 0,   p_nsum + 0,
                               p_ids + 0 * NTOK * KSTR, p_vals + 0 * NTOK * KSTR, p_cnt + 0 * NTOK);
    gate_kernel<<<NTOK, 256>>>(p_hall + 128, 384, p_tau3 + 1, 3, qk_emb, p_ce,            6, 512,
                               p_cfreq + 64,  p_nsum + 4096,
                               p_ids + 1 * NTOK * KSTR, p_vals + 1 * NTOK * KSTR, p_cnt + 1 * NTOK);
    gate_kernel<<<NTOK, 256>>>(p_hall + 256, 384, p_tau3 + 2, 3, v_emb,  p_ce + 64 * DS,  6, 512,
                               p_cfreq + 128, p_nsum + 8192,
                               p_ids + 2 * NTOK * KSTR, p_vals + 2 * NTOK * KSTR, p_cnt + 2 * NTOK);

    // 4. sparse emits -> Q, K, V (fp16 neuron rows)
    emit_kernel<<<NTOK, 256>>>(p_h1, p_qkn, p_ids + 0 * NTOK * KSTR, p_vals + 0 * NTOK * KSTR,
                               p_cnt + 0 * NTOK, nullptr, p_Qm);
    emit_kernel<<<NTOK, 256>>>(p_h1, p_qkn, p_ids + 1 * NTOK * KSTR, p_vals + 1 * NTOK * KSTR,
                               p_cnt + 1 * NTOK, nullptr, p_Km);
    emit_kernel<<<NTOK, 256>>>(p_h1, p_vn,  p_ids + 2 * NTOK * KSTR, p_vals + 2 * NTOK * KSTR,
                               p_cnt + 2 * NTOK, nullptr, p_Vm);

    // 5. attention
    {
        const int smem = (3 * 64 * ATPAD + 64 * 64) * (int)sizeof(float);
        cudaFuncSetAttribute(attn_kernel, cudaFuncAttributeMaxDynamicSharedMemorySize, smem);
        dim3 g(BB * NHEAD, SQ / 64);
        attn_kernel<<<g, 256, smem>>>(p_Qm, p_Km, p_Vm, p_attn);
    }

    // 6. O-projection + residual
    {
        dim3 g(DM / 64, NTOK / 64);
        sgemm_kernel<<<g, 256>>>(p_attn, expand_O, nullptr, x, p_xmid, NTOK, DM, DM);
    }

    // 7. LN2, know projection + gate + emit (+ residual) -> d_out
    ln_kernel<<<NTOK, 256>>>(p_xmid, ln2_scale, ln2_bias, p_h2);
    {
        dim3 g(DS / 64, NTOK / 64);
        sgemm_kernel<<<g, 256>>>(p_h2, proj_know_k, proj_know_b, nullptr, p_hknow, NTOK, DS, DM);
    }
    tau_kernel<<<NTOK, 32>>>(p_h2, tau_know_k, tau_know_b, p_tauk, 1);
    gate_kernel<<<NTOK, 256>>>(p_hknow, DS, p_tauk, 1, kn_emb, p_ce + 128 * DS, 7, 1024,
                               p_cfreq + 192, p_nsum + 12288,
                               p_ids + 3 * NTOK * KSTR, p_vals + 3 * NTOK * KSTR, p_cnt + 3 * NTOK);
    emit_kernel<<<NTOK, 256>>>(p_h2, p_kn, p_ids + 3 * NTOK * KSTR, p_vals + 3 * NTOK * KSTR,
                               p_cnt + 3 * NTOK, p_xmid, out);

    // 8. aux scalar
    if (out_size > NTOK * DM)
        aux_kernel<<<1, 256>>>(p_cfreq, p_nsum, out + (size_t)NTOK * DM);
}